// round 1
// baseline (speedup 1.0000x reference)
#include <cuda_runtime.h>
#include <cuda_bf16.h>

// HeadDetectorLoss: single-pass streaming reduction over N rows.
//   inputs (metadata order): prediction (N,6) f32, target_class (N,) i32, target_box (N,4) f32
//   output: scalar f32
//
// class_loss = mean over rows of [logsumexp(l0,l1) - l[tc]]
// box_loss   = sum over rows with tc!=0 of mean_j (pred[2+j]-tb[j])^2
// result     = class_loss + 10 * box_loss / (1e-6 + count(tc!=0))
//
// Rows are processed in PAIRS so every global load is a 128-bit LDG:
//   2 rows of prediction = 48 B = 3 x float4 (48*p is 16-aligned)
//   2 rows of target_box = 32 B = 2 x float4
//   2 target classes     = int2

#define NBLOCKS  2048
#define NTHREADS 256

__device__ double       g_nll  = 0.0;
__device__ double       g_box  = 0.0;
__device__ double       g_msk  = 0.0;
__device__ unsigned int g_done = 0u;

__global__ __launch_bounds__(NTHREADS)
void head_loss_kernel(const float* __restrict__ pred,
                      const int*   __restrict__ tcls,
                      const float* __restrict__ tbox,
                      float*       __restrict__ out,
                      int n)
{
    const float4* __restrict__ p4 = reinterpret_cast<const float4*>(pred);
    const float4* __restrict__ b4 = reinterpret_cast<const float4*>(tbox);
    const int2*   __restrict__ c2 = reinterpret_cast<const int2*>(tcls);
    const int pairs = n >> 1;

    float nll = 0.f, box = 0.f, msk = 0.f;

    const int stride = gridDim.x * blockDim.x;
    for (int p = blockIdx.x * blockDim.x + threadIdx.x; p < pairs; p += stride) {
        // issue all loads up front -> 6 independent LDG.128/64 in flight (MLP)
        const float4 a  = p4[3 * p + 0];   // row0: l0 l1 b0 b1
        const float4 b  = p4[3 * p + 1];   // row0: b2 b3 | row1: l0 l1
        const float4 c  = p4[3 * p + 2];   // row1: b0 b1 b2 b3
        const int2   tc = c2[p];
        const float4 t0 = b4[2 * p + 0];
        const float4 t1 = b4[2 * p + 1];

        // ---- row 0 ----
        {
            const float l0 = a.x, l1 = a.y;
            const float hi = fmaxf(l0, l1), lo = fminf(l0, l1);
            const float lse = hi + log1pf(__expf(lo - hi));
            nll += lse - (tc.x == 0 ? l0 : l1);
            if (tc.x != 0) {
                const float d0 = a.z - t0.x, d1 = a.w - t0.y;
                const float d2 = b.x - t0.z, d3 = b.y - t0.w;
                box += 0.25f * ((d0 * d0 + d1 * d1) + (d2 * d2 + d3 * d3));
                msk += 1.f;
            }
        }
        // ---- row 1 ----
        {
            const float l0 = b.z, l1 = b.w;
            const float hi = fmaxf(l0, l1), lo = fminf(l0, l1);
            const float lse = hi + log1pf(__expf(lo - hi));
            nll += lse - (tc.y == 0 ? l0 : l1);
            if (tc.y != 0) {
                const float d0 = c.x - t1.x, d1 = c.y - t1.y;
                const float d2 = c.z - t1.z, d3 = c.w - t1.w;
                box += 0.25f * ((d0 * d0 + d1 * d1) + (d2 * d2 + d3 * d3));
                msk += 1.f;
            }
        }
    }

    // tail row if n is odd (not hit for N=4194304, kept for generality)
    if ((n & 1) && blockIdx.x == 0 && threadIdx.x == 0) {
        const int i = n - 1;
        const float l0 = pred[6 * i + 0], l1 = pred[6 * i + 1];
        const float hi = fmaxf(l0, l1), lo = fminf(l0, l1);
        const float lse = hi + log1pf(__expf(lo - hi));
        const int tc = tcls[i];
        nll += lse - (tc == 0 ? l0 : l1);
        if (tc != 0) {
            float s = 0.f;
            #pragma unroll
            for (int j = 0; j < 4; j++) {
                const float d = pred[6 * i + 2 + j] - tbox[4 * i + j];
                s += d * d;
            }
            box += 0.25f * s;
            msk += 1.f;
        }
    }

    // ---- intra-warp reduction ----
    #pragma unroll
    for (int o = 16; o > 0; o >>= 1) {
        nll += __shfl_down_sync(0xffffffffu, nll, o);
        box += __shfl_down_sync(0xffffffffu, box, o);
        msk += __shfl_down_sync(0xffffffffu, msk, o);
    }

    // ---- intra-block reduction ----
    __shared__ float s_nll[NTHREADS / 32], s_box[NTHREADS / 32], s_msk[NTHREADS / 32];
    const int lane = threadIdx.x & 31;
    const int warp = threadIdx.x >> 5;
    if (lane == 0) { s_nll[warp] = nll; s_box[warp] = box; s_msk[warp] = msk; }
    __syncthreads();

    if (threadIdx.x == 0) {
        float tn = 0.f, tb = 0.f, tm = 0.f;
        #pragma unroll
        for (int w = 0; w < NTHREADS / 32; w++) { tn += s_nll[w]; tb += s_box[w]; tm += s_msk[w]; }

        atomicAdd(&g_nll, (double)tn);
        atomicAdd(&g_box, (double)tb);
        atomicAdd(&g_msk, (double)tm);
        __threadfence();
        const unsigned v = atomicAdd(&g_done, 1u);
        if (v == gridDim.x - 1) {
            // last block: all partials are globally visible now
            __threadfence();
            const double sn = atomicAdd(&g_nll, 0.0);   // coherent read
            const double sb = atomicAdd(&g_box, 0.0);
            const double sm = atomicAdd(&g_msk, 0.0);
            const double cls = sn / (double)n;
            const double res = cls + 10.0 * sb / (1e-6 + sm);
            out[0] = (float)res;
            // reset for the next graph replay (kernel-exit implies membar)
            g_nll = 0.0; g_box = 0.0; g_msk = 0.0; g_done = 0u;
        }
    }
}

extern "C" void kernel_launch(void* const* d_in, const int* in_sizes, int n_in,
                              void* d_out, int out_size)
{
    const float* pred = (const float*)d_in[0];
    const int*   tcls = (const int*)  d_in[1];
    const float* tbox = (const float*)d_in[2];
    float*       out  = (float*)d_out;
    const int n = in_sizes[1];   // element count of target_class == N

    head_loss_kernel<<<NBLOCKS, NTHREADS>>>(pred, tcls, tbox, out, n);
}

// round 3
// speedup vs baseline: 1.0088x; 1.0088x over previous
#include <cuda_runtime.h>
#include <cuda_bf16.h>

// HeadDetectorLoss: single-pass streaming reduction over N rows.
//   inputs (metadata order): prediction (N,6) f32, target_class (N,) i32, target_box (N,4) f32
//   output: scalar f32
//
// result = mean(logsumexp(l0,l1) - l[tc]) + 10 * sum_masked(mse)/ (1e-6 + count)
//
// Rows processed in PAIRS (2 rows = 48B pred = 3xfloat4, 32B box = 2xfloat4,
// 8B cls = int2) so every load is wide. Loop manually unrolled x2 so 12
// independent loads are batched per iteration (MLP), and the 2-class
// logsumexp uses fast MUFU math (__logf/__expf) to keep the issue pipe quiet.

#define NBLOCKS  2048
#define NTHREADS 256

__device__ double       g_nll  = 0.0;
__device__ double       g_box  = 0.0;
__device__ double       g_msk  = 0.0;
__device__ unsigned int g_done = 0u;

// process one PAIR given its 6 loaded vectors
__device__ __forceinline__ void do_pair(const float4 a, const float4 b, const float4 c,
                                        const int2 tc, const float4 t0, const float4 t1,
                                        float& nll, float& box, float& msk)
{
    // row 0: logits a.x,a.y ; box pred a.z,a.w,b.x,b.y ; target t0
    {
        const float l0 = a.x, l1 = a.y;
        const float hi = fmaxf(l0, l1), lo = fminf(l0, l1);
        const float lse = hi + __logf(1.0f + __expf(lo - hi));
        nll += lse - (tc.x == 0 ? l0 : l1);
        if (tc.x != 0) {
            const float d0 = a.z - t0.x, d1 = a.w - t0.y;
            const float d2 = b.x - t0.z, d3 = b.y - t0.w;
            box += 0.25f * ((d0 * d0 + d1 * d1) + (d2 * d2 + d3 * d3));
            msk += 1.f;
        }
    }
    // row 1: logits b.z,b.w ; box pred c ; target t1
    {
        const float l0 = b.z, l1 = b.w;
        const float hi = fmaxf(l0, l1), lo = fminf(l0, l1);
        const float lse = hi + __logf(1.0f + __expf(lo - hi));
        nll += lse - (tc.y == 0 ? l0 : l1);
        if (tc.y != 0) {
            const float d0 = c.x - t1.x, d1 = c.y - t1.y;
            const float d2 = c.z - t1.z, d3 = c.w - t1.w;
            box += 0.25f * ((d0 * d0 + d1 * d1) + (d2 * d2 + d3 * d3));
            msk += 1.f;
        }
    }
}

__global__ __launch_bounds__(NTHREADS)
void head_loss_kernel(const float* __restrict__ pred,
                      const int*   __restrict__ tcls,
                      const float* __restrict__ tbox,
                      float*       __restrict__ out,
                      int n)
{
    const float4* __restrict__ p4 = reinterpret_cast<const float4*>(pred);
    const float4* __restrict__ b4 = reinterpret_cast<const float4*>(tbox);
    const int2*   __restrict__ c2 = reinterpret_cast<const int2*>(tcls);
    const int pairs = n >> 1;

    float nll = 0.f, box = 0.f, msk = 0.f;

    const int stride = gridDim.x * blockDim.x;
    int p = blockIdx.x * blockDim.x + threadIdx.x;

    // main unrolled-x2 loop: 12 independent wide loads batched up front
    for (; p + stride < pairs; p += 2 * stride) {
        const int q = p + stride;

        const float4 a0 = __ldcs(&p4[3 * p + 0]);
        const float4 b0 = __ldcs(&p4[3 * p + 1]);
        const float4 c0 = __ldcs(&p4[3 * p + 2]);
        const float4 a1 = __ldcs(&p4[3 * q + 0]);
        const float4 b1 = __ldcs(&p4[3 * q + 1]);
        const float4 c1 = __ldcs(&p4[3 * q + 2]);
        const int2   e0 = __ldcs(&c2[p]);
        const int2   e1 = __ldcs(&c2[q]);
        const float4 u0 = __ldcs(&b4[2 * p + 0]);
        const float4 v0 = __ldcs(&b4[2 * p + 1]);
        const float4 u1 = __ldcs(&b4[2 * q + 0]);
        const float4 v1 = __ldcs(&b4[2 * q + 1]);

        do_pair(a0, b0, c0, e0, u0, v0, nll, box, msk);
        do_pair(a1, b1, c1, e1, u1, v1, nll, box, msk);
    }
    // remainder pairs (0 or 1 per thread)
    for (; p < pairs; p += stride) {
        const float4 a = __ldcs(&p4[3 * p + 0]);
        const float4 b = __ldcs(&p4[3 * p + 1]);
        const float4 c = __ldcs(&p4[3 * p + 2]);
        const int2   e = __ldcs(&c2[p]);
        const float4 u = __ldcs(&b4[2 * p + 0]);
        const float4 v = __ldcs(&b4[2 * p + 1]);
        do_pair(a, b, c, e, u, v, nll, box, msk);
    }

    // odd tail row (not hit for N=4194304)
    if ((n & 1) && blockIdx.x == 0 && threadIdx.x == 0) {
        const int i = n - 1;
        const float l0 = pred[6 * i + 0], l1 = pred[6 * i + 1];
        const float hi = fmaxf(l0, l1), lo = fminf(l0, l1);
        const float lse = hi + __logf(1.0f + __expf(lo - hi));
        const int tc = tcls[i];
        nll += lse - (tc == 0 ? l0 : l1);
        if (tc != 0) {
            float s = 0.f;
            #pragma unroll
            for (int j = 0; j < 4; j++) {
                const float d = pred[6 * i + 2 + j] - tbox[4 * i + j];
                s += d * d;
            }
            box += 0.25f * s;
            msk += 1.f;
        }
    }

    // ---- intra-warp reduction ----
    #pragma unroll
    for (int o = 16; o > 0; o >>= 1) {
        nll += __shfl_down_sync(0xffffffffu, nll, o);
        box += __shfl_down_sync(0xffffffffu, box, o);
        msk += __shfl_down_sync(0xffffffffu, msk, o);
    }

    // ---- intra-block reduction ----
    __shared__ float s_nll[NTHREADS / 32], s_box[NTHREADS / 32], s_msk[NTHREADS / 32];
    const int lane = threadIdx.x & 31;
    const int warp = threadIdx.x >> 5;
    if (lane == 0) { s_nll[warp] = nll; s_box[warp] = box; s_msk[warp] = msk; }
    __syncthreads();

    if (threadIdx.x == 0) {
        float tn = 0.f, tb = 0.f, tm = 0.f;
        #pragma unroll
        for (int w = 0; w < NTHREADS / 32; w++) { tn += s_nll[w]; tb += s_box[w]; tm += s_msk[w]; }

        atomicAdd(&g_nll, (double)tn);
        atomicAdd(&g_box, (double)tb);
        atomicAdd(&g_msk, (double)tm);
        __threadfence();
        const unsigned v = atomicAdd(&g_done, 1u);
        if (v == gridDim.x - 1) {
            __threadfence();
            const double sn = atomicAdd(&g_nll, 0.0);
            const double sb = atomicAdd(&g_box, 0.0);
            const double sm = atomicAdd(&g_msk, 0.0);
            const double cls = sn / (double)n;
            const double res = cls + 10.0 * sb / (1e-6 + sm);
            out[0] = (float)res;
            g_nll = 0.0; g_box = 0.0; g_msk = 0.0; g_done = 0u;
        }
    }
}

extern "C" void kernel_launch(void* const* d_in, const int* in_sizes, int n_in,
                              void* d_out, int out_size)
{
    const float* pred = (const float*)d_in[0];
    const int*   tcls = (const int*)  d_in[1];
    const float* tbox = (const float*)d_in[2];
    float*       out  = (float*)d_out;
    const int n = in_sizes[1];   // element count of target_class == N

    head_loss_kernel<<<NBLOCKS, NTHREADS>>>(pred, tcls, tbox, out, n);
}

// round 4
// speedup vs baseline: 1.1228x; 1.1131x over previous
#include <cuda_runtime.h>
#include <cuda_bf16.h>

// HeadDetectorLoss: single-pass streaming reduction, smem-staged.
//   inputs: prediction (N,6) f32, target_class (N,) i32, target_box (N,4) f32
//   output: scalar f32
//   result = mean(lse(l0,l1) - l[tc]) + 10 * sum_masked(mse) / (1e-6 + count)
//
// R3 showed DRAM pinned at ~67% regardless of issue/occupancy: the 48B-strided
// per-thread float4 pattern makes each warp LDG span ~12 cache lines (3x the
// L1tex wavefronts, 50% sector use), throttling outstanding requests.
// Fix: one block = one 1024-row tile; ALL global loads are coalesced 16B
// cp.async.cg (L1-bypass) into smem; threads then read their rows from smem.

#define NTHREADS       256
#define ROWS_PER_TILE  1024
#define PAIRS_PER_TILE (ROWS_PER_TILE / 2)          // 512 -> 2 pairs/thread
#define PRED_F4_TILE   (ROWS_PER_TILE * 3 / 2)      // 1536
#define BOX_F4_TILE    (ROWS_PER_TILE)              // 1024
#define CLS_I4_TILE    (ROWS_PER_TILE / 4)          // 256

__device__ double       g_nll  = 0.0;
__device__ double       g_box  = 0.0;
__device__ double       g_msk  = 0.0;
__device__ unsigned int g_done = 0u;

__device__ __forceinline__ void cp16(void* smem_dst, const void* gmem_src)
{
    unsigned s = (unsigned)__cvta_generic_to_shared(smem_dst);
    asm volatile("cp.async.cg.shared.global [%0], [%1], 16;\n"
                 :: "r"(s), "l"(gmem_src) : "memory");
}

// one row: logits l0,l1 ; box pred d* vs target t* ; class tc
__device__ __forceinline__ void do_row(float l0, float l1,
                                       float p0, float p1, float p2, float p3,
                                       float t0, float t1, float t2, float t3,
                                       int tc, float& nll, float& box, float& msk)
{
    const float hi = fmaxf(l0, l1), lo = fminf(l0, l1);
    const float lse = hi + __logf(1.0f + __expf(lo - hi));
    nll += lse - (tc == 0 ? l0 : l1);
    if (tc != 0) {
        const float d0 = p0 - t0, d1 = p1 - t1, d2 = p2 - t2, d3 = p3 - t3;
        box += 0.25f * ((d0 * d0 + d1 * d1) + (d2 * d2 + d3 * d3));
        msk += 1.f;
    }
}

__global__ __launch_bounds__(NTHREADS)
void head_loss_kernel(const float* __restrict__ pred,
                      const int*   __restrict__ tcls,
                      const float* __restrict__ tbox,
                      float*       __restrict__ out,
                      int n)
{
    __shared__ float4 s_pred[PRED_F4_TILE];   // 24576 B
    __shared__ float4 s_box [BOX_F4_TILE];    // 16384 B
    __shared__ int4   s_cls [CLS_I4_TILE];    //  4096 B

    const int tid = threadIdx.x;
    const long base_row = (long)blockIdx.x * ROWS_PER_TILE;
    const int rows_rem  = (int)min((long)ROWS_PER_TILE, (long)n - base_row);

    // valid 16B-chunk counts for this tile
    const int pred_f4 = (3 * rows_rem + 1) >> 1;   // ceil(rows*24/16)
    const int box_f4  = rows_rem;                  // 16B per row
    const int cls_i4  = (rows_rem + 3) >> 2;       // ceil(rows*4/16)

    // ---- coalesced async load: every lane's address is +16B from its neighbor ----
    const float4* gp = (const float4*)pred + (base_row * 3 >> 1);
    const float4* gb = (const float4*)tbox + base_row;
    const int4*   gc = (const int4*)  tcls + (base_row >> 2);

    #pragma unroll
    for (int k = 0; k < 6; k++) {
        const int i = tid + k * NTHREADS;
        if (i < pred_f4) cp16(&s_pred[i], &gp[i]);
    }
    #pragma unroll
    for (int k = 0; k < 4; k++) {
        const int i = tid + k * NTHREADS;
        if (i < box_f4) cp16(&s_box[i], &gb[i]);
    }
    if (tid < cls_i4) cp16(&s_cls[tid], &gc[tid]);

    asm volatile("cp.async.commit_group;\n" ::: "memory");
    asm volatile("cp.async.wait_group 0;\n" ::: "memory");
    __syncthreads();

    // ---- compute: thread handles pairs tid and tid+256 of this tile ----
    float nll = 0.f, box = 0.f, msk = 0.f;
    const int2* s_c2 = reinterpret_cast<const int2*>(s_cls);

    #pragma unroll
    for (int k = 0; k < 2; k++) {
        const int p = tid + k * NTHREADS;           // pair index in tile
        const long r0 = base_row + 2 * p;           // global row of pair's first row
        if (r0 >= n) continue;

        const float4 a = s_pred[3 * p + 0];         // row0: l0 l1 b0 b1
        const float4 b = s_pred[3 * p + 1];         // row0: b2 b3 | row1: l0 l1
        const float4 c = s_pred[3 * p + 2];         // row1: b0 b1 b2 b3
        const float4 u = s_box[2 * p + 0];
        const float4 v = s_box[2 * p + 1];
        const int2  tc = s_c2[p];

        do_row(a.x, a.y, a.z, a.w, b.x, b.y, u.x, u.y, u.z, u.w, tc.x, nll, box, msk);
        if (r0 + 1 < n)
            do_row(b.z, b.w, c.x, c.y, c.z, c.w, v.x, v.y, v.z, v.w, tc.y, nll, box, msk);
    }

    // ---- intra-warp reduction ----
    #pragma unroll
    for (int o = 16; o > 0; o >>= 1) {
        nll += __shfl_down_sync(0xffffffffu, nll, o);
        box += __shfl_down_sync(0xffffffffu, box, o);
        msk += __shfl_down_sync(0xffffffffu, msk, o);
    }

    // ---- intra-block reduction ----
    __shared__ float r_nll[NTHREADS / 32], r_box[NTHREADS / 32], r_msk[NTHREADS / 32];
    const int lane = tid & 31, warp = tid >> 5;
    if (lane == 0) { r_nll[warp] = nll; r_box[warp] = box; r_msk[warp] = msk; }
    __syncthreads();

    if (tid == 0) {
        float tn = 0.f, tb = 0.f, tm = 0.f;
        #pragma unroll
        for (int w = 0; w < NTHREADS / 32; w++) { tn += r_nll[w]; tb += r_box[w]; tm += r_msk[w]; }

        atomicAdd(&g_nll, (double)tn);
        atomicAdd(&g_box, (double)tb);
        atomicAdd(&g_msk, (double)tm);
        __threadfence();
        const unsigned v = atomicAdd(&g_done, 1u);
        if (v == gridDim.x - 1) {
            __threadfence();
            const double sn = atomicAdd(&g_nll, 0.0);
            const double sb = atomicAdd(&g_box, 0.0);
            const double sm = atomicAdd(&g_msk, 0.0);
            const double res = sn / (double)n + 10.0 * sb / (1e-6 + sm);
            out[0] = (float)res;
            g_nll = 0.0; g_box = 0.0; g_msk = 0.0; g_done = 0u;   // reset for next replay
        }
    }
}

extern "C" void kernel_launch(void* const* d_in, const int* in_sizes, int n_in,
                              void* d_out, int out_size)
{
    const float* pred = (const float*)d_in[0];
    const int*   tcls = (const int*)  d_in[1];
    const float* tbox = (const float*)d_in[2];
    float*       out  = (float*)d_out;
    const int n = in_sizes[1];                         // N (target_class count)

    const int nblocks = (n + ROWS_PER_TILE - 1) / ROWS_PER_TILE;   // 4096 for N=4M
    head_loss_kernel<<<nblocks, NTHREADS>>>(pred, tcls, tbox, out, n);
}